// round 3
// baseline (speedup 1.0000x reference)
#include <cuda_runtime.h>
#include <cstdint>

#define S 512
#define Hd 256
#define Bb 4
#define TT 8
#define HC 16

// Scratch (no cudaMalloc allowed): 2MB + 2MB
__device__ float g_ht[Bb * S * Hd];        // [b][t][h], b_h folded in
__device__ float g_htpT[Bb * Hd * S];      // [b][h][t']  (transposed projection)

__device__ __forceinline__ float tanh_fast(float x) {
    float y;
    asm("tanh.approx.f32 %0, %1;" : "=f"(y) : "f"(x));
    return y;
}

// ---------------------------------------------------------------------------
// K1: fused projection GEMM.  C[m][n] = sum_k h[m][k] * Wcat[k][n]
//   m in [0,2048) = b*512+t,  n in [0,512): n<256 -> W_t (ht out, +b_h),
//   n>=256 -> W_t_prime (htpT out, transposed store).
// 64x64 tile, BK=16, 256 threads, 4x4 microtile.
// ---------------------------------------------------------------------------
__global__ __launch_bounds__(256) void proj_kernel(
    const float* __restrict__ h, const float* __restrict__ Wt,
    const float* __restrict__ Wtp, const float* __restrict__ bh)
{
    __shared__ float As[64][17];
    __shared__ float Bs[16][64];

    const int tid = threadIdx.x;
    const int tx = tid & 15, ty = tid >> 4;
    const int m0 = blockIdx.x * 64;
    const int ny = blockIdx.y;
    const float* __restrict__ W = (ny < 4) ? Wt : Wtp;
    const int col0 = (ny & 3) * 64;

    const int lm  = tid >> 2;         // 0..63 (A row)
    const int lk4 = (tid & 3) * 4;    // A k offset
    const int lbk = tid >> 6;         // 0..3  (B k row)
    const int lbn = tid & 63;         // B col

    float acc[4][4] = {};

    for (int k0 = 0; k0 < Hd; k0 += 16) {
        float4 av = *reinterpret_cast<const float4*>(
            &h[(size_t)(m0 + lm) * Hd + k0 + lk4]);
        As[lm][lk4 + 0] = av.x; As[lm][lk4 + 1] = av.y;
        As[lm][lk4 + 2] = av.z; As[lm][lk4 + 3] = av.w;
#pragma unroll
        for (int kk = 0; kk < 16; kk += 4)
            Bs[lbk + kk][lbn] = W[(size_t)(k0 + lbk + kk) * Hd + col0 + lbn];
        __syncthreads();
#pragma unroll
        for (int k = 0; k < 16; ++k) {
            float4 bv = *reinterpret_cast<const float4*>(&Bs[k][tx * 4]);
#pragma unroll
            for (int i = 0; i < 4; ++i) {
                float a = As[ty * 4 + i][k];
                acc[i][0] += a * bv.x; acc[i][1] += a * bv.y;
                acc[i][2] += a * bv.z; acc[i][3] += a * bv.w;
            }
        }
        __syncthreads();
    }

    const int m = m0 + ty * 4;
    const int n = col0 + tx * 4;
    if (ny < 4) {
        float4 bh4 = *reinterpret_cast<const float4*>(&bh[n]);
#pragma unroll
        for (int i = 0; i < 4; ++i) {
            float4 o = make_float4(acc[i][0] + bh4.x, acc[i][1] + bh4.y,
                                   acc[i][2] + bh4.z, acc[i][3] + bh4.w);
            *reinterpret_cast<float4*>(&g_ht[(size_t)(m + i) * Hd + n]) = o;
        }
    } else {
        const int b = m0 >> 9;
        const int t = m - b * S;
#pragma unroll
        for (int j = 0; j < 4; ++j)
#pragma unroll
            for (int i = 0; i < 4; ++i)
                g_htpT[((size_t)b * Hd + n + j) * S + t + i] = acc[i][j];
    }
}

// ---------------------------------------------------------------------------
// K2: scores (tanh / MUFU-bound) + sigmoid + softmax + output matvec.
// One CTA per (b, 8-row t tile). 512 threads; thread = one t' column.
// ---------------------------------------------------------------------------
struct K2Smem {
    float w[TT][S];       // exp/weights (never aliased)
    float sums[TT];
    union {
        struct { float ht[TT][Hd]; float htp[HC][S]; float wa[Hd]; } p1;
        float4 red[TT][S];  // 64KB partial-output combine
    } u;
};

__global__ __launch_bounds__(512, 2) void attn_kernel(
    const float* __restrict__ h, const float* __restrict__ Wa,
    const float* __restrict__ ba, float* __restrict__ out)
{
    extern __shared__ char smem_raw[];
    K2Smem& sm = *reinterpret_cast<K2Smem*>(smem_raw);
    const int tid = threadIdx.x;
    const int b = blockIdx.x >> 6;
    const int t0 = (blockIdx.x & 63) * TT;

    // Stage ht tile (8KB) and W_a
    const float* __restrict__ htg = &g_ht[((size_t)b * S + t0) * Hd];
    float* htf = &sm.u.p1.ht[0][0];
    for (int i = tid; i < TT * Hd; i += 512) htf[i] = htg[i];
    if (tid < Hd) sm.u.p1.wa[tid] = Wa[tid];

    // ---- score phase: MUFU-bound ----
    float acc[TT] = {};
    for (int h0 = 0; h0 < Hd; h0 += HC) {
        __syncthreads();
#pragma unroll
        for (int j = 0; j < HC; ++j)
            sm.u.p1.htp[j][tid] = g_htpT[((size_t)b * Hd + h0 + j) * S + tid];
        __syncthreads();
#pragma unroll 4
        for (int j = 0; j < HC; ++j) {
            float hv = sm.u.p1.htp[j][tid];
            float wa = sm.u.p1.wa[h0 + j];
#pragma unroll
            for (int t = 0; t < TT; ++t)
                acc[t] += wa * tanh_fast(sm.u.p1.ht[t][h0 + j] + hv);
        }
    }

    // ---- sigmoid + exp ----
    const float ba_v = ba[0];
    float e[TT];
#pragma unroll
    for (int t = 0; t < TT; ++t) {
        float x = acc[t] + ba_v;
        float sg = 0.5f * tanh_fast(0.5f * x) + 0.5f;   // sigmoid via HW tanh
        e[t] = __expf(sg);                               // sg in (0,1): no max-sub needed
        sm.w[t][tid] = e[t];
    }
    __syncthreads();

    // ---- per-t row sums (warp w reduces row w) ----
    const int warp = tid >> 5, lane = tid & 31;
    if (warp < TT) {
        float s = 0.f;
#pragma unroll
        for (int i = 0; i < S; i += 32) s += sm.w[warp][i + lane];
#pragma unroll
        for (int o = 16; o > 0; o >>= 1) s += __shfl_xor_sync(0xffffffffu, s, o);
        if (lane == 0) sm.sums[warp] = s;
    }
    __syncthreads();

    // ---- normalize, write attention weights ----
    float* __restrict__ wout = out + (size_t)Bb * S * Hd;
#pragma unroll
    for (int t = 0; t < TT; ++t) {
        float wv = e[t] / sm.sums[t];
        sm.w[t][tid] = wv;
        wout[((size_t)b * S + t0 + t) * S + tid] = wv;
    }
    __syncthreads();

    // ---- output matvec: out[t][:] = sum_tp w[t][tp] * h[b][tp][:] ----
    // thread = (tp-group g of 64, h-quad hq). Each h element read exactly once.
    const int g = tid >> 6, hq = tid & 63;
    const float4* __restrict__ h4 = reinterpret_cast<const float4*>(h);
    float4 o[TT];
#pragma unroll
    for (int t = 0; t < TT; ++t) o[t] = make_float4(0.f, 0.f, 0.f, 0.f);
    const int tp0 = g * 64;
    for (int it = 0; it < 64; ++it) {
        const int tp = tp0 + it;
        float4 v = h4[((size_t)b * S + tp) * (Hd / 4) + hq];
#pragma unroll
        for (int t = 0; t < TT; ++t) {
            float wv = sm.w[t][tp];
            o[t].x += wv * v.x; o[t].y += wv * v.y;
            o[t].z += wv * v.z; o[t].w += wv * v.w;
        }
    }
    // combine the 8 tp-group partials via smem (union region; p1 dead by now)
#pragma unroll
    for (int t = 0; t < TT; ++t) sm.u.red[g][t * 64 + hq] = o[t];
    __syncthreads();
    float4 r = make_float4(0.f, 0.f, 0.f, 0.f);
#pragma unroll
    for (int gg = 0; gg < 8; ++gg) {
        float4 p = sm.u.red[gg][tid];
        r.x += p.x; r.y += p.y; r.z += p.z; r.w += p.w;
    }
    const int tt = tid >> 6, hh = tid & 63;
    reinterpret_cast<float4*>(out)[((size_t)b * S + t0 + tt) * (Hd / 4) + hh] = r;
}

// ---------------------------------------------------------------------------
extern "C" void kernel_launch(void* const* d_in, const int* in_sizes, int n_in,
                              void* d_out, int out_size) {
    (void)in_sizes; (void)n_in; (void)out_size;
    const float* h   = (const float*)d_in[0];
    const float* Wt  = (const float*)d_in[1];
    const float* Wtp = (const float*)d_in[2];
    const float* bh  = (const float*)d_in[3];
    const float* Wa  = (const float*)d_in[4];
    const float* ba  = (const float*)d_in[5];
    float* out = (float*)d_out;

    cudaFuncSetAttribute(attn_kernel,
                         cudaFuncAttributeMaxDynamicSharedMemorySize,
                         (int)sizeof(K2Smem));

    dim3 g1(32, 8);
    proj_kernel<<<g1, 256>>>(h, Wt, Wtp, bh);
    attn_kernel<<<Bb * (S / TT), 512, sizeof(K2Smem)>>>(h, Wa, ba, out);
}